// round 2
// baseline (speedup 1.0000x reference)
#include <cuda_runtime.h>
#include <cuda_bf16.h>

// ---------------- problem constants ----------------
#define HID 128
#define HEADS 4
#define HD 32            // head dim
#define NEG_SLOPE 0.2f
#define BN_EPS 1e-5f
#define NMAX 100096

// ---------------- scratch (device globals; no allocation allowed) ----------
__device__ __align__(16) float    g_h[NMAX * HID];      // h = x @ W
__device__ __align__(16) float    g_acc[NMAX * HID];    // aggregation accumulator (init to bias)
__device__ __align__(16) float    g_xbuf[NMAX * HID];   // layer output / next input
__device__ __align__(16) float    g_as[NMAX * HEADS];   // att_src dot
__device__ __align__(16) float    g_ad[NMAX * HEADS];   // att_dst dot
__device__ __align__(16) float    g_denom[NMAX * HEADS];
__device__ __align__(16) unsigned g_emax[NMAX * HEADS]; // flipped-float max

// ---------------- helpers ----------------
__device__ __forceinline__ float lrelu(float v) { return v > 0.f ? v : NEG_SLOPE * v; }

// order-preserving float<->uint for atomicMax
__device__ __forceinline__ unsigned fflip(float f) {
    unsigned u = __float_as_uint(f);
    return u ^ ((unsigned)((int)u >> 31) | 0x80000000u);
}
__device__ __forceinline__ float funflip(unsigned v) {
    unsigned u = (v & 0x80000000u) ? (v ^ 0x80000000u) : ~v;
    return __uint_as_float(u);
}

__device__ __forceinline__ void red_add_v4(float* p, float4 v) {
    asm volatile("red.global.add.v4.f32 [%0], {%1,%2,%3,%4};"
                 :: "l"(p), "f"(v.x), "f"(v.y), "f"(v.z), "f"(v.w) : "memory");
}

// ---------------- GEMM: h = x @ W[l], plus a_s/a_d dots, plus per-node init --
// block: 256 threads, computes 64 rows x 128 cols. smem: W (64KB) + X tile (32KB)
__global__ void gemm_kernel(const float* __restrict__ xext, int use_xbuf,
                            const float* __restrict__ W,
                            const float* __restrict__ att_s,
                            const float* __restrict__ att_d,
                            const float* __restrict__ bias,
                            int N)
{
    extern __shared__ float sh[];
    float* Ws = sh;                // 128*128
    float* Xs = sh + HID * HID;    // 64*128

    const float* x = use_xbuf ? g_xbuf : xext;

    int tid = threadIdx.x;
    int tx = tid & 31, ty = tid >> 5;
    int row0 = blockIdx.x * 64;

    float4* Ws4 = (float4*)Ws;
    const float4* W4 = (const float4*)W;
    #pragma unroll 4
    for (int i = tid; i < HID * HID / 4; i += 256) Ws4[i] = W4[i];

    float4* Xs4 = (float4*)Xs;
    const float4* x4 = (const float4*)x;
    #pragma unroll 2
    for (int i = tid; i < 64 * 32; i += 256) {
        int r = i >> 5, k4 = i & 31;
        int row = row0 + r;
        Xs4[i] = (row < N) ? x4[(long long)row * 32 + k4] : make_float4(0.f, 0.f, 0.f, 0.f);
    }
    __syncthreads();

    float4 acc[8];
    #pragma unroll
    for (int r = 0; r < 8; r++) acc[r] = make_float4(0.f, 0.f, 0.f, 0.f);

    #pragma unroll 2
    for (int k = 0; k < HID; k++) {
        float4 w = Ws4[k * 32 + tx];
        #pragma unroll
        for (int r = 0; r < 8; r++) {
            float xv = Xs[(ty + r * 8) * HID + k];
            acc[r].x = fmaf(xv, w.x, acc[r].x);
            acc[r].y = fmaf(xv, w.y, acc[r].y);
            acc[r].z = fmaf(xv, w.z, acc[r].z);
            acc[r].w = fmaf(xv, w.w, acc[r].w);
        }
    }

    float4 attS = ((const float4*)att_s)[tx];
    float4 attD = ((const float4*)att_d)[tx];
    float4 b4   = ((const float4*)bias)[tx];

    #pragma unroll
    for (int r = 0; r < 8; r++) {
        int row = row0 + ty + r * 8;
        if (row < N) {
            ((float4*)g_h)[(long long)row * 32 + tx]   = acc[r];
            ((float4*)g_acc)[(long long)row * 32 + tx] = b4;   // bias pre-loaded into accumulator
            float ps = acc[r].x * attS.x + acc[r].y * attS.y + acc[r].z * attS.z + acc[r].w * attS.w;
            float pd = acc[r].x * attD.x + acc[r].y * attD.y + acc[r].z * attD.z + acc[r].w * attD.w;
            // reduce over 8 lanes per head (head = tx/8)
            ps += __shfl_down_sync(0xffffffffu, ps, 4, 8);
            ps += __shfl_down_sync(0xffffffffu, ps, 2, 8);
            ps += __shfl_down_sync(0xffffffffu, ps, 1, 8);
            pd += __shfl_down_sync(0xffffffffu, pd, 4, 8);
            pd += __shfl_down_sync(0xffffffffu, pd, 2, 8);
            pd += __shfl_down_sync(0xffffffffu, pd, 1, 8);
            if ((tx & 7) == 0) {
                g_as[row * HEADS + (tx >> 3)] = ps;
                g_ad[row * HEADS + (tx >> 3)] = pd;
            }
            if (tx < HEADS) {
                g_emax[row * HEADS + tx] = 0u;   // below fflip of any finite float
                g_denom[row * HEADS + tx] = 0.f;
            }
        }
    }
}

// ---------------- edge pass 1: segment max ----------------
__global__ void edge_max_kernel(const int* __restrict__ ei, int E, int Etot)
{
    int i = blockIdx.x * blockDim.x + threadIdx.x;
    if (i >= Etot) return;
    int s, d;
    if (i < E) { s = ei[i]; d = ei[E + i]; } else { s = d = i - E; }
    float4 as = ((const float4*)g_as)[s];
    float4 ad = ((const float4*)g_ad)[d];
    unsigned* em = &g_emax[(long long)d * HEADS];
    atomicMax(&em[0], fflip(lrelu(as.x + ad.x)));
    atomicMax(&em[1], fflip(lrelu(as.y + ad.y)));
    atomicMax(&em[2], fflip(lrelu(as.z + ad.z)));
    atomicMax(&em[3], fflip(lrelu(as.w + ad.w)));
}

// ---------------- edge pass 2: exp + segment sum ----------------
__global__ void edge_sum_kernel(const int* __restrict__ ei, int E, int Etot)
{
    int i = blockIdx.x * blockDim.x + threadIdx.x;
    if (i >= Etot) return;
    int s, d;
    if (i < E) { s = ei[i]; d = ei[E + i]; } else { s = d = i - E; }
    float4 as = ((const float4*)g_as)[s];
    float4 ad = ((const float4*)g_ad)[d];
    const unsigned* em = &g_emax[(long long)d * HEADS];
    float4 p;
    p.x = __expf(lrelu(as.x + ad.x) - funflip(em[0]));
    p.y = __expf(lrelu(as.y + ad.y) - funflip(em[1]));
    p.z = __expf(lrelu(as.z + ad.z) - funflip(em[2]));
    p.w = __expf(lrelu(as.w + ad.w) - funflip(em[3]));
    red_add_v4(&g_denom[(long long)d * HEADS], p);
}

// ---------------- edge pass 3: message aggregation (warp per edge) --------
__global__ void edge_msg_kernel(const int* __restrict__ ei, int E, int Etot)
{
    long long gidx = (long long)blockIdx.x * blockDim.x + threadIdx.x;
    long long e = gidx >> 5;
    int lane = (int)(gidx & 31);
    if (e >= Etot) return;
    int s, d;
    if (e < E) { s = ei[e]; d = ei[E + e]; } else { s = d = (int)(e - E); }
    int h = lane >> 3;
    float ev = lrelu(g_as[(long long)s * HEADS + h] + g_ad[(long long)d * HEADS + h]);
    float m  = funflip(g_emax[(long long)d * HEADS + h]);
    float p  = __expf(ev - m);
    float alpha = p / (g_denom[(long long)d * HEADS + h] + 1e-16f);
    float4 v = ((const float4*)g_h)[(long long)s * 32 + lane];
    v.x *= alpha; v.y *= alpha; v.z *= alpha; v.w *= alpha;
    red_add_v4(&g_acc[(long long)d * HID + lane * 4], v);
}

// ---------------- post: relu + batchnorm ----------------
__global__ void post_kernel(const float* __restrict__ gamma, const float* __restrict__ beta,
                            const float* __restrict__ mean, const float* __restrict__ var,
                            int N)
{
    int i = blockIdx.x * blockDim.x + threadIdx.x;   // over N*32 float4 elems
    if (i >= N * 32) return;
    int c4 = i & 31;
    float4 v  = ((const float4*)g_acc)[i];
    float4 gm = ((const float4*)gamma)[c4];
    float4 bt = ((const float4*)beta)[c4];
    float4 mu = ((const float4*)mean)[c4];
    float4 vr = ((const float4*)var)[c4];
    float4 r;
    r.x = (fmaxf(v.x, 0.f) - mu.x) * (gm.x * rsqrtf(vr.x + BN_EPS)) + bt.x;
    r.y = (fmaxf(v.y, 0.f) - mu.y) * (gm.y * rsqrtf(vr.y + BN_EPS)) + bt.y;
    r.z = (fmaxf(v.z, 0.f) - mu.z) * (gm.z * rsqrtf(vr.z + BN_EPS)) + bt.z;
    r.w = (fmaxf(v.w, 0.f) - mu.w) * (gm.w * rsqrtf(vr.w + BN_EPS)) + bt.w;
    ((float4*)g_xbuf)[i] = r;
}

// ---------------- pool (batch is sorted) + MLP head ----------------
__global__ void pool_mlp_kernel(const int* __restrict__ batch,
                                const float* __restrict__ Wh1, const float* __restrict__ bh1,
                                const float* __restrict__ Wh2, const float* __restrict__ bh2,
                                float* __restrict__ out, int N)
{
    int g = blockIdx.x;
    int t = threadIdx.x;   // 128 threads
    __shared__ float pooled[HID];
    __shared__ float hdn[64];
    __shared__ int bounds[2];

    if (t < 2) {
        int target = g + t;
        int lo = 0, hi = N;
        while (lo < hi) {
            int mid = (lo + hi) >> 1;
            if (batch[mid] < target) lo = mid + 1; else hi = mid;
        }
        bounds[t] = lo;
    }
    __syncthreads();
    int s = bounds[0], epos = bounds[1];

    float acc = 0.f;
    for (int n = s; n < epos; n++) acc += g_xbuf[(long long)n * HID + t];
    float cnt = (float)((epos - s) > 1 ? (epos - s) : 1);
    pooled[t] = acc / cnt;
    __syncthreads();

    if (t < 64) {
        float a = bh1[t];
        #pragma unroll 4
        for (int c = 0; c < HID; c++) a = fmaf(pooled[c], Wh1[c * 64 + t], a);
        hdn[t] = fmaxf(a, 0.f);
    }
    __syncthreads();

    if (t < 32) {
        float a = hdn[t] * Wh2[t] + hdn[t + 32] * Wh2[t + 32];
        #pragma unroll
        for (int off = 16; off; off >>= 1) a += __shfl_down_sync(0xffffffffu, a, off);
        if (t == 0) out[g] = a + bh2[0];
    }
}

// ---------------- launch ----------------
extern "C" void kernel_launch(void* const* d_in, const int* in_sizes, int n_in,
                              void* d_out, int out_size)
{
    const float* x       = (const float*)d_in[0];
    const int*   ei      = (const int*)d_in[1];
    const int*   batch   = (const int*)d_in[2];
    const float* W       = (const float*)d_in[3];
    const float* att_src = (const float*)d_in[4];
    const float* att_dst = (const float*)d_in[5];
    const float* bias    = (const float*)d_in[6];
    const float* gamma   = (const float*)d_in[7];
    const float* beta    = (const float*)d_in[8];
    const float* bn_mean = (const float*)d_in[9];
    const float* bn_var  = (const float*)d_in[10];
    const float* Wh1     = (const float*)d_in[11];
    const float* bh1     = (const float*)d_in[12];
    const float* Wh2     = (const float*)d_in[13];
    const float* bh2     = (const float*)d_in[14];

    int N = in_sizes[0] / HID;
    int E = in_sizes[1] / 2;
    int Etot = E + N;
    int G = out_size;

    const int SMEM = (HID * HID + 64 * HID) * (int)sizeof(float);   // 96KB
    cudaFuncSetAttribute(gemm_kernel, cudaFuncAttributeMaxDynamicSharedMemorySize, SMEM);

    int gemm_blocks = (N + 63) / 64;
    int edge_blocks = (Etot + 255) / 256;
    long long msg_threads = (long long)Etot * 32;
    int msg_blocks = (int)((msg_threads + 255) / 256);
    int post_blocks = (N * 32 + 255) / 256;

    for (int l = 0; l < 3; l++) {
        gemm_kernel<<<gemm_blocks, 256, SMEM>>>(x, l > 0,
                                                W + (long long)l * HID * HID,
                                                att_src + l * HID, att_dst + l * HID,
                                                bias + l * HID, N);
        edge_max_kernel<<<edge_blocks, 256>>>(ei, E, Etot);
        edge_sum_kernel<<<edge_blocks, 256>>>(ei, E, Etot);
        edge_msg_kernel<<<msg_blocks, 256>>>(ei, E, Etot);
        post_kernel<<<post_blocks, 256>>>(gamma + l * HID, beta + l * HID,
                                          bn_mean + l * HID, bn_var + l * HID, N);
    }
    pool_mlp_kernel<<<G, 128>>>(batch, Wh1, bh1, Wh2, bh2, (float*)d_out, N);
}

// round 3
// speedup vs baseline: 2.0079x; 2.0079x over previous
#include <cuda_runtime.h>
#include <cuda_bf16.h>
#include <math_constants.h>

// ---------------- problem constants ----------------
#define HID 128
#define HEADS 4
#define NEG_SLOPE 0.2f
#define BN_EPS 1e-5f
#define NMAX 100096
#define ETOTMAX 1800192

// ---------------- scratch (device globals; no allocation allowed) ----------
__device__ __align__(16) float g_h[NMAX * HID];      // h = x @ W
__device__ __align__(16) float g_xbuf[NMAX * HID];   // layer output / next input
__device__ __align__(16) float g_as[NMAX * HEADS];   // att_src dot
__device__ __align__(16) float g_ad[NMAX * HEADS];   // att_dst dot
// CSR scratch
__device__ int g_counts[NMAX];
__device__ int g_rowptr[NMAX + 1];
__device__ int g_fill[NMAX];
__device__ int g_csrc[ETOTMAX];
__device__ int g_bsum[1024];

__device__ __forceinline__ float lrelu(float v) { return v > 0.f ? v : NEG_SLOPE * v; }

// ---------------- CSR build ----------------
__global__ void zero_kernel(int N)
{
    int i = blockIdx.x * blockDim.x + threadIdx.x;
    if (i < N) g_counts[i] = 0;
}

__global__ void hist_kernel(const int* __restrict__ ei, int E, int Etot)
{
    int i = blockIdx.x * blockDim.x + threadIdx.x;
    if (i >= Etot) return;
    int d = (i < E) ? ei[E + i] : (i - E);
    atomicAdd(&g_counts[d], 1);
}

// block-level exclusive scan, 1024 items/block
__global__ void scan1_kernel(int N)
{
    __shared__ int sh[1024];
    int tid = threadIdx.x;
    int gid = blockIdx.x * 1024 + tid;
    int v = (gid < N) ? g_counts[gid] : 0;
    sh[tid] = v;
    __syncthreads();
    // Hillis-Steele inclusive
    #pragma unroll
    for (int off = 1; off < 1024; off <<= 1) {
        int t = (tid >= off) ? sh[tid - off] : 0;
        __syncthreads();
        sh[tid] += t;
        __syncthreads();
    }
    if (gid <= N) g_rowptr[gid] = sh[tid] - v;   // exclusive
    if (tid == 1023) g_bsum[blockIdx.x] = sh[tid];
}

__global__ void scan2_kernel(int nb)
{
    __shared__ int sh[1024];
    int tid = threadIdx.x;
    int v = (tid < nb) ? g_bsum[tid] : 0;
    sh[tid] = v;
    __syncthreads();
    #pragma unroll
    for (int off = 1; off < 1024; off <<= 1) {
        int t = (tid >= off) ? sh[tid - off] : 0;
        __syncthreads();
        sh[tid] += t;
        __syncthreads();
    }
    if (tid < nb) g_bsum[tid] = sh[tid] - v;     // exclusive
}

__global__ void scan3_kernel(int N, int Etot)
{
    int gid = blockIdx.x * blockDim.x + threadIdx.x;
    if (gid < N) {
        int r = g_rowptr[gid] + g_bsum[gid >> 10];
        g_rowptr[gid] = r;
        g_fill[gid] = r;
    }
    if (gid == 0) g_rowptr[N] = Etot;
}

__global__ void scatter_kernel(const int* __restrict__ ei, int E, int Etot)
{
    int i = blockIdx.x * blockDim.x + threadIdx.x;
    if (i >= Etot) return;
    int s, d;
    if (i < E) { s = ei[i]; d = ei[E + i]; } else { s = d = i - E; }
    int pos = atomicAdd(&g_fill[d], 1);
    g_csrc[pos] = s;
}

// ---------------- GEMM: h = x @ W[l] + attention dots ----------------
// block: 256 threads, 64 rows x 128 cols. smem: W (64KB) + X tile (32KB)
__global__ void gemm_kernel(const float* __restrict__ xext, int use_xbuf,
                            const float* __restrict__ W,
                            const float* __restrict__ att_s,
                            const float* __restrict__ att_d,
                            int N)
{
    extern __shared__ float sh[];
    float* Ws = sh;                // 128*128
    float* Xs = sh + HID * HID;    // 64*128

    const float* x = use_xbuf ? g_xbuf : xext;

    int tid = threadIdx.x;
    int tx = tid & 31, ty = tid >> 5;
    int row0 = blockIdx.x * 64;

    float4* Ws4 = (float4*)Ws;
    const float4* W4 = (const float4*)W;
    #pragma unroll 4
    for (int i = tid; i < HID * HID / 4; i += 256) Ws4[i] = W4[i];

    float4* Xs4 = (float4*)Xs;
    const float4* x4 = (const float4*)x;
    #pragma unroll 2
    for (int i = tid; i < 64 * 32; i += 256) {
        int r = i >> 5, k4 = i & 31;
        int row = row0 + r;
        Xs4[i] = (row < N) ? x4[(size_t)row * 32 + k4] : make_float4(0.f, 0.f, 0.f, 0.f);
    }
    __syncthreads();

    float4 acc[8];
    #pragma unroll
    for (int r = 0; r < 8; r++) acc[r] = make_float4(0.f, 0.f, 0.f, 0.f);

    #pragma unroll 2
    for (int k = 0; k < HID; k++) {
        float4 w = Ws4[k * 32 + tx];
        #pragma unroll
        for (int r = 0; r < 8; r++) {
            float xv = Xs[(ty + r * 8) * HID + k];
            acc[r].x = fmaf(xv, w.x, acc[r].x);
            acc[r].y = fmaf(xv, w.y, acc[r].y);
            acc[r].z = fmaf(xv, w.z, acc[r].z);
            acc[r].w = fmaf(xv, w.w, acc[r].w);
        }
    }

    float4 attS = ((const float4*)att_s)[tx];
    float4 attD = ((const float4*)att_d)[tx];

    #pragma unroll
    for (int r = 0; r < 8; r++) {
        int row = row0 + ty + r * 8;
        if (row < N) {
            ((float4*)g_h)[(size_t)row * 32 + tx] = acc[r];
            float ps = acc[r].x * attS.x + acc[r].y * attS.y + acc[r].z * attS.z + acc[r].w * attS.w;
            float pd = acc[r].x * attD.x + acc[r].y * attD.y + acc[r].z * attD.z + acc[r].w * attD.w;
            ps += __shfl_down_sync(0xffffffffu, ps, 4, 8);
            ps += __shfl_down_sync(0xffffffffu, ps, 2, 8);
            ps += __shfl_down_sync(0xffffffffu, ps, 1, 8);
            pd += __shfl_down_sync(0xffffffffu, pd, 4, 8);
            pd += __shfl_down_sync(0xffffffffu, pd, 2, 8);
            pd += __shfl_down_sync(0xffffffffu, pd, 1, 8);
            if ((tx & 7) == 0) {
                g_as[row * HEADS + (tx >> 3)] = ps;
                g_ad[row * HEADS + (tx >> 3)] = pd;
            }
        }
    }
}

// ---------------- fused aggregation: online softmax + weighted sum + bias + relu + BN
// one warp per destination node; accumulator in registers (float4/lane = 128 ch/warp)
__global__ __launch_bounds__(256) void agg_kernel(const float* __restrict__ bias,
                           const float* __restrict__ gamma, const float* __restrict__ beta,
                           const float* __restrict__ mean, const float* __restrict__ var,
                           int N)
{
    int w = (blockIdx.x * blockDim.x + threadIdx.x) >> 5;
    int lane = threadIdx.x & 31;
    if (w >= N) return;
    int n = w;
    int h = lane >> 3;

    int beg = g_rowptr[n];
    int end = g_rowptr[n + 1];
    float ad_h = g_ad[n * HEADS + h];

    float m = -CUDART_INF_F;
    float den = 0.f;
    float4 acc = make_float4(0.f, 0.f, 0.f, 0.f);

    int s = (beg < end) ? g_csrc[beg] : 0;
    for (int i = beg; i < end; i++) {
        int s_next = (i + 1 < end) ? g_csrc[i + 1] : 0;
        float as_h = __ldg(&g_as[s * HEADS + h]);
        float4 hv = ((const float4*)g_h)[(size_t)s * 32 + lane];
        float e = lrelu(as_h + ad_h);
        float nm = fmaxf(m, e);
        float scale = __expf(m - nm);     // exp(-inf)=0 on first iter
        float p = __expf(e - nm);
        den = den * scale + p;
        acc.x = acc.x * scale + p * hv.x;
        acc.y = acc.y * scale + p * hv.y;
        acc.z = acc.z * scale + p * hv.z;
        acc.w = acc.w * scale + p * hv.w;
        m = nm;
        s = s_next;
    }

    float inv = 1.f / (den + 1e-16f);
    float4 b4 = ((const float4*)bias)[lane];
    float4 gm = ((const float4*)gamma)[lane];
    float4 bt = ((const float4*)beta)[lane];
    float4 mu = ((const float4*)mean)[lane];
    float4 vr = ((const float4*)var)[lane];

    float4 r;
    r.x = (fmaxf(acc.x * inv + b4.x, 0.f) - mu.x) * (gm.x * rsqrtf(vr.x + BN_EPS)) + bt.x;
    r.y = (fmaxf(acc.y * inv + b4.y, 0.f) - mu.y) * (gm.y * rsqrtf(vr.y + BN_EPS)) + bt.y;
    r.z = (fmaxf(acc.z * inv + b4.z, 0.f) - mu.z) * (gm.z * rsqrtf(vr.z + BN_EPS)) + bt.z;
    r.w = (fmaxf(acc.w * inv + b4.w, 0.f) - mu.w) * (gm.w * rsqrtf(vr.w + BN_EPS)) + bt.w;
    ((float4*)g_xbuf)[(size_t)n * 32 + lane] = r;
}

// ---------------- pool (batch is sorted) + MLP head ----------------
__global__ void pool_mlp_kernel(const int* __restrict__ batch,
                                const float* __restrict__ Wh1, const float* __restrict__ bh1,
                                const float* __restrict__ Wh2, const float* __restrict__ bh2,
                                float* __restrict__ out, int N)
{
    int g = blockIdx.x;
    int t = threadIdx.x;   // 128 threads
    __shared__ float pooled[HID];
    __shared__ float hdn[64];
    __shared__ int bounds[2];

    if (t < 2) {
        int target = g + t;
        int lo = 0, hi = N;
        while (lo < hi) {
            int mid = (lo + hi) >> 1;
            if (batch[mid] < target) lo = mid + 1; else hi = mid;
        }
        bounds[t] = lo;
    }
    __syncthreads();
    int s = bounds[0], epos = bounds[1];

    float acc = 0.f;
    for (int n = s; n < epos; n++) acc += g_xbuf[(size_t)n * HID + t];
    float cnt = (float)((epos - s) > 1 ? (epos - s) : 1);
    pooled[t] = acc / cnt;
    __syncthreads();

    if (t < 64) {
        float a = bh1[t];
        #pragma unroll 4
        for (int c = 0; c < HID; c++) a = fmaf(pooled[c], Wh1[c * 64 + t], a);
        hdn[t] = fmaxf(a, 0.f);
    }
    __syncthreads();

    if (t < 32) {
        float a = hdn[t] * Wh2[t] + hdn[t + 32] * Wh2[t + 32];
        #pragma unroll
        for (int off = 16; off; off >>= 1) a += __shfl_down_sync(0xffffffffu, a, off);
        if (t == 0) out[g] = a + bh2[0];
    }
}

// ---------------- launch ----------------
extern "C" void kernel_launch(void* const* d_in, const int* in_sizes, int n_in,
                              void* d_out, int out_size)
{
    const float* x       = (const float*)d_in[0];
    const int*   ei      = (const int*)d_in[1];
    const int*   batch   = (const int*)d_in[2];
    const float* W       = (const float*)d_in[3];
    const float* att_src = (const float*)d_in[4];
    const float* att_dst = (const float*)d_in[5];
    const float* bias    = (const float*)d_in[6];
    const float* gamma   = (const float*)d_in[7];
    const float* beta    = (const float*)d_in[8];
    const float* bn_mean = (const float*)d_in[9];
    const float* bn_var  = (const float*)d_in[10];
    const float* Wh1     = (const float*)d_in[11];
    const float* bh1     = (const float*)d_in[12];
    const float* Wh2     = (const float*)d_in[13];
    const float* bh2     = (const float*)d_in[14];

    int N = in_sizes[0] / HID;
    int E = in_sizes[1] / 2;
    int Etot = E + N;
    int G = out_size;

    const int SMEM = (HID * HID + 64 * HID) * (int)sizeof(float);   // 96KB
    cudaFuncSetAttribute(gemm_kernel, cudaFuncAttributeMaxDynamicSharedMemorySize, SMEM);

    int gemm_blocks = (N + 63) / 64;
    int edge_blocks = (Etot + 255) / 256;
    int node_blocks = (N + 255) / 256;
    int scan_blocks = (N + 1023) / 1024;
    int agg_blocks  = (N * 32 + 255) / 256;   // warp per node

    // --- CSR build (once; reused by all 3 layers) ---
    zero_kernel<<<node_blocks, 256>>>(N);
    hist_kernel<<<edge_blocks, 256>>>(ei, E, Etot);
    scan1_kernel<<<scan_blocks, 1024>>>(N);
    scan2_kernel<<<1, 1024>>>(scan_blocks);
    scan3_kernel<<<node_blocks, 256>>>(N, Etot);
    scatter_kernel<<<edge_blocks, 256>>>(ei, E, Etot);

    for (int l = 0; l < 3; l++) {
        gemm_kernel<<<gemm_blocks, 256, SMEM>>>(x, l > 0,
                                                W + (size_t)l * HID * HID,
                                                att_src + l * HID, att_dst + l * HID, N);
        agg_kernel<<<agg_blocks, 256>>>(bias + l * HID,
                                        gamma + l * HID, beta + l * HID,
                                        bn_mean + l * HID, bn_var + l * HID, N);
    }
    pool_mlp_kernel<<<G, 128>>>(batch, Wh1, bh1, Wh2, bh2, (float*)d_out, N);
}

// round 5
// speedup vs baseline: 2.2194x; 1.1053x over previous
#include <cuda_runtime.h>
#include <cuda_bf16.h>
#include <math_constants.h>

// ---------------- problem constants ----------------
#define HID 128
#define HEADS 4
#define NEG_SLOPE 0.2f
#define BN_EPS 1e-5f
#define NMAX 100096
#define ETOTMAX 1800192

// ---------------- scratch (device globals; no allocation allowed) ----------
__device__ __align__(16) float g_h[NMAX * HID];      // h = x @ W
__device__ __align__(16) float g_xbuf[NMAX * HID];   // layer output / next input
__device__ __align__(16) float g_as[NMAX * HEADS];   // att_src dot
__device__ __align__(16) float g_ad[NMAX * HEADS];   // att_dst dot
__device__ __align__(16) float4 g_wfragh[4096];      // W hi (tf32) in mma B-frag order
__device__ __align__(16) float4 g_wfragl[4096];      // W lo residual (tf32)
// CSR scratch
__device__ int g_counts[NMAX];
__device__ int g_rowptr[NMAX + 1];
__device__ int g_fill[NMAX];
__device__ int g_csrc[ETOTMAX];
__device__ int g_bsum[1024];

__device__ __forceinline__ float lrelu(float v) { return v > 0.f ? v : NEG_SLOPE * v; }

__device__ __forceinline__ unsigned f2tf32(float f) {
    unsigned r;
    asm("cvt.rna.tf32.f32 %0, %1;" : "=r"(r) : "f"(f));
    return r;
}

__device__ __forceinline__ void mma_tf32(float* c, unsigned a0, unsigned a1,
                                         unsigned a2, unsigned a3,
                                         unsigned b0, unsigned b1) {
    asm volatile(
        "mma.sync.aligned.m16n8k8.row.col.f32.tf32.tf32.f32 "
        "{%0,%1,%2,%3},{%4,%5,%6,%7},{%8,%9},{%0,%1,%2,%3};"
        : "+f"(c[0]), "+f"(c[1]), "+f"(c[2]), "+f"(c[3])
        : "r"(a0), "r"(a1), "r"(a2), "r"(a3), "r"(b0), "r"(b1));
}

// ---------------- CSR build ----------------
__global__ void zero_kernel(int N)
{
    int i = blockIdx.x * blockDim.x + threadIdx.x;
    if (i < N) g_counts[i] = 0;
}

__global__ void hist_kernel(const int* __restrict__ ei, int E, int Etot)
{
    int i = blockIdx.x * blockDim.x + threadIdx.x;
    if (i >= Etot) return;
    int d = (i < E) ? ei[E + i] : (i - E);
    atomicAdd(&g_counts[d], 1);
}

__global__ void scan1_kernel(int N)
{
    __shared__ int sh[1024];
    int tid = threadIdx.x;
    int gid = blockIdx.x * 1024 + tid;
    int v = (gid < N) ? g_counts[gid] : 0;
    sh[tid] = v;
    __syncthreads();
    #pragma unroll
    for (int off = 1; off < 1024; off <<= 1) {
        int t = (tid >= off) ? sh[tid - off] : 0;
        __syncthreads();
        sh[tid] += t;
        __syncthreads();
    }
    if (gid <= N) g_rowptr[gid] = sh[tid] - v;   // exclusive
    if (tid == 1023) g_bsum[blockIdx.x] = sh[tid];
}

__global__ void scan2_kernel(int nb)
{
    __shared__ int sh[1024];
    int tid = threadIdx.x;
    int v = (tid < nb) ? g_bsum[tid] : 0;
    sh[tid] = v;
    __syncthreads();
    #pragma unroll
    for (int off = 1; off < 1024; off <<= 1) {
        int t = (tid >= off) ? sh[tid - off] : 0;
        __syncthreads();
        sh[tid] += t;
        __syncthreads();
    }
    if (tid < nb) g_bsum[tid] = sh[tid] - v;     // exclusive
}

__global__ void scan3_kernel(int N, int Etot)
{
    int gid = blockIdx.x * blockDim.x + threadIdx.x;
    if (gid < N) {
        int r = g_rowptr[gid] + g_bsum[gid >> 10];
        g_rowptr[gid] = r;
        g_fill[gid] = r;
    }
    if (gid == 0) g_rowptr[N] = Etot;
}

__global__ void scatter_kernel(const int* __restrict__ ei, int E, int Etot)
{
    int i = blockIdx.x * blockDim.x + threadIdx.x;
    if (i >= Etot) return;
    int s, d;
    if (i < E) { s = ei[i]; d = ei[E + i]; } else { s = d = i - E; }
    int pos = atomicAdd(&g_fill[d], 1);
    g_csrc[pos] = s;
}

// ---------------- W -> mma B-fragment order, hi/lo tf32 split ----------------
// layout: frag[(ks*8 + v)*32 + lane] packs B frags for ntiles {2v, 2v+1}:
//   {b[2v][0], b[2v][1], b[2v+1][0], b[2v+1][1]}
// where b[nt][j] = tf32(W[(ks*8 + lane%4 + j*4)*128 + nt*8 + lane/4])
__global__ void wfrag_kernel(const float* __restrict__ W)
{
    int i = blockIdx.x * 256 + threadIdx.x;
    if (i >= 4096) return;
    int ks = i >> 8;
    int v = (i >> 5) & 7;
    int lane = i & 31;
    int krow = ks * 8 + (lane & 3);
    int n0 = (2 * v) * 8 + (lane >> 2);
    int n1 = n0 + 8;
    float w0 = W[krow * HID + n0];
    float w1 = W[(krow + 4) * HID + n0];
    float w2 = W[krow * HID + n1];
    float w3 = W[(krow + 4) * HID + n1];
    float4 hi, lo;
    hi.x = __uint_as_float(f2tf32(w0)); lo.x = __uint_as_float(f2tf32(w0 - hi.x));
    hi.y = __uint_as_float(f2tf32(w1)); lo.y = __uint_as_float(f2tf32(w1 - hi.y));
    hi.z = __uint_as_float(f2tf32(w2)); lo.z = __uint_as_float(f2tf32(w2 - hi.z));
    hi.w = __uint_as_float(f2tf32(w3)); lo.w = __uint_as_float(f2tf32(w3 - hi.w));
    g_wfragh[i] = hi;
    g_wfragl[i] = lo;
}

// ---------------- 3xTF32 tensor-core GEMM: h = x @ W[l] + attention dots ----
// block: 256 threads / 8 warps; block tile 128 rows x 128 cols.
// warp w owns rows [blk*128 + 16w, +16), all 128 cols (16 n-tiles of 8).
__global__ __launch_bounds__(256) void gemm_tf32_kernel(
    const float* __restrict__ xext, int use_xbuf,
    const float* __restrict__ att_s, const float* __restrict__ att_d, int N)
{
    extern __shared__ float4 sW[];      // [0,4096) hi, [4096,8192) lo : 128KB
    float4* sWh = sW;
    float4* sWl = sW + 4096;

    const float* __restrict__ x = use_xbuf ? g_xbuf : xext;

    int tid = threadIdx.x;
    int lane = tid & 31;
    int wid = tid >> 5;

    #pragma unroll 4
    for (int i = tid; i < 4096; i += 256) { sWh[i] = g_wfragh[i]; sWl[i] = g_wfragl[i]; }
    __syncthreads();

    int row0 = blockIdx.x * 128 + wid * 16;
    int g = lane >> 2;
    int cl = lane & 3;
    int r0 = row0 + g;
    int r1 = r0 + 8;
    bool v0 = r0 < N, v1 = r1 < N;

    float c[16][4];
    #pragma unroll
    for (int t = 0; t < 16; t++) {
        c[t][0] = 0.f; c[t][1] = 0.f; c[t][2] = 0.f; c[t][3] = 0.f;
    }

    const float* xr0 = x + (size_t)r0 * HID;
    const float* xr1 = x + (size_t)r1 * HID;

    for (int ks = 0; ks < 16; ks++) {
        int k0 = ks * 8 + cl;
        float f0 = v0 ? __ldg(xr0 + k0)     : 0.f;
        float f2 = v0 ? __ldg(xr0 + k0 + 4) : 0.f;
        float f1 = v1 ? __ldg(xr1 + k0)     : 0.f;
        float f3 = v1 ? __ldg(xr1 + k0 + 4) : 0.f;
        unsigned ah0 = f2tf32(f0), ah1 = f2tf32(f1), ah2 = f2tf32(f2), ah3 = f2tf32(f3);
        unsigned al0 = f2tf32(f0 - __uint_as_float(ah0));
        unsigned al1 = f2tf32(f1 - __uint_as_float(ah1));
        unsigned al2 = f2tf32(f2 - __uint_as_float(ah2));
        unsigned al3 = f2tf32(f3 - __uint_as_float(ah3));
        #pragma unroll
        for (int v = 0; v < 8; v++) {
            float4 bh = sWh[(ks * 8 + v) * 32 + lane];
            float4 bl = sWl[(ks * 8 + v) * 32 + lane];
            unsigned bh0 = __float_as_uint(bh.x), bh1 = __float_as_uint(bh.y);
            unsigned bh2 = __float_as_uint(bh.z), bh3 = __float_as_uint(bh.w);
            unsigned bl0 = __float_as_uint(bl.x), bl1 = __float_as_uint(bl.y);
            unsigned bl2 = __float_as_uint(bl.z), bl3 = __float_as_uint(bl.w);
            // Ah*Bh + Ah*Bl + Al*Bh
            mma_tf32(c[2 * v],     ah0, ah1, ah2, ah3, bh0, bh1);
            mma_tf32(c[2 * v],     ah0, ah1, ah2, ah3, bl0, bl1);
            mma_tf32(c[2 * v],     al0, al1, al2, al3, bh0, bh1);
            mma_tf32(c[2 * v + 1], ah0, ah1, ah2, ah3, bh2, bh3);
            mma_tf32(c[2 * v + 1], ah0, ah1, ah2, ah3, bl2, bl3);
            mma_tf32(c[2 * v + 1], al0, al1, al2, al3, bh2, bh3);
        }
    }

    // store h (fp32)
    #pragma unroll
    for (int nt = 0; nt < 16; nt++) {
        int cb = nt * 8 + cl * 2;
        if (v0) *(float2*)&g_h[(size_t)r0 * HID + cb] = make_float2(c[nt][0], c[nt][1]);
        if (v1) *(float2*)&g_h[(size_t)r1 * HID + cb] = make_float2(c[nt][2], c[nt][3]);
    }

    // attention dots per head (head h = ntiles 4h..4h+3)
    #pragma unroll
    for (int h = 0; h < HEADS; h++) {
        float s0 = 0.f, d0 = 0.f, s1 = 0.f, d1 = 0.f;
        #pragma unroll
        for (int t = 0; t < 4; t++) {
            int nt = h * 4 + t;
            int cb = nt * 8 + cl * 2;
            float w0 = att_s[cb], w1 = att_s[cb + 1];
            float u0 = att_d[cb], u1 = att_d[cb + 1];
            s0 += c[nt][0] * w0 + c[nt][1] * w1;
            d0 += c[nt][0] * u0 + c[nt][1] * u1;
            s1 += c[nt][2] * w0 + c[nt][3] * w1;
            d1 += c[nt][2] * u0 + c[nt][3] * u1;
        }
        s0 += __shfl_down_sync(0xffffffffu, s0, 2, 4); s0 += __shfl_down_sync(0xffffffffu, s0, 1, 4);
        d0 += __shfl_down_sync(0xffffffffu, d0, 2, 4); d0 += __shfl_down_sync(0xffffffffu, d0, 1, 4);
        s1 += __shfl_down_sync(0xffffffffu, s1, 2, 4); s1 += __shfl_down_sync(0xffffffffu, s1, 1, 4);
        d1 += __shfl_down_sync(0xffffffffu, d1, 2, 4); d1 += __shfl_down_sync(0xffffffffu, d1, 1, 4);
        if (cl == 0) {
            if (v0) { g_as[r0 * HEADS + h] = s0; g_ad[r0 * HEADS + h] = d0; }
            if (v1) { g_as[r1 * HEADS + h] = s1; g_ad[r1 * HEADS + h] = d1; }
        }
    }
}

// ---------------- fused aggregation: online softmax + weighted sum + bias + relu + BN
__global__ __launch_bounds__(256) void agg_kernel(const float* __restrict__ bias,
                           const float* __restrict__ gamma, const float* __restrict__ beta,
                           const float* __restrict__ mean, const float* __restrict__ var,
                           int N)
{
    int w = (blockIdx.x * blockDim.x + threadIdx.x) >> 5;
    int lane = threadIdx.x & 31;
    if (w >= N) return;
    int n = w;
    int h = lane >> 3;

    int beg = g_rowptr[n];
    int end = g_rowptr[n + 1];
    float ad_h = g_ad[n * HEADS + h];

    float m = -CUDART_INF_F;
    float den = 0.f;
    float4 acc = make_float4(0.f, 0.f, 0.f, 0.f);

    int s = (beg < end) ? g_csrc[beg] : 0;
    for (int i = beg; i < end; i++) {
        int s_next = (i + 1 < end) ? g_csrc[i + 1] : 0;
        float as_h = __ldg(&g_as[s * HEADS + h]);
        float4 hv = ((const float4*)g_h)[(size_t)s * 32 + lane];
        float e = lrelu(as_h + ad_h);
        float nm = fmaxf(m, e);
        float scale = __expf(m - nm);
        float p = __expf(e - nm);
        den = den * scale + p;
        acc.x = acc.x * scale + p * hv.x;
        acc.y = acc.y * scale + p * hv.y;
        acc.z = acc.z * scale + p * hv.z;
        acc.w = acc.w * scale + p * hv.w;
        m = nm;
        s = s_next;
    }

    float inv = 1.f / (den + 1e-16f);
    float4 b4 = ((const float4*)bias)[lane];
    float4 gm = ((const float4*)gamma)[lane];
    float4 bt = ((const float4*)beta)[lane];
    float4 mu = ((const float4*)mean)[lane];
    float4 vr = ((const float4*)var)[lane];

    float4 r;
    r.x = (fmaxf(acc.x * inv + b4.x, 0.f) - mu.x) * (gm.x * rsqrtf(vr.x + BN_EPS)) + bt.x;
    r.y = (fmaxf(acc.y * inv + b4.y, 0.f) - mu.y) * (gm.y * rsqrtf(vr.y + BN_EPS)) + bt.y;
    r.z = (fmaxf(acc.z * inv + b4.z, 0.f) - mu.z) * (gm.z * rsqrtf(vr.z + BN_EPS)) + bt.z;
    r.w = (fmaxf(acc.w * inv + b4.w, 0.f) - mu.w) * (gm.w * rsqrtf(vr.w + BN_EPS)) + bt.w;
    ((float4*)g_xbuf)[(size_t)n * 32 + lane] = r;
}

// ---------------- pool (batch is sorted) + MLP head ----------------
__global__ void pool_mlp_kernel(const int* __restrict__ batch,
                                const float* __restrict__ Wh1, const float* __restrict__ bh1,
                                const float* __restrict__ Wh2, const float* __restrict__ bh2,
                                float* __restrict__ out, int N)
{
    int g = blockIdx.x;
    int t = threadIdx.x;   // 128 threads
    __shared__ float pooled[HID];
    __shared__ float hdn[64];
    __shared__ int bounds[2];

    if (t < 2) {
        int target = g + t;
        int lo = 0, hi = N;
        while (lo < hi) {
            int mid = (lo + hi) >> 1;
            if (batch[mid] < target) lo = mid + 1; else hi = mid;
        }
        bounds[t] = lo;
    }
    __syncthreads();
    int s = bounds[0], epos = bounds[1];

    float acc = 0.f;
    for (int n = s; n < epos; n++) acc += g_xbuf[(size_t)n * HID + t];
    float cnt = (float)((epos - s) > 1 ? (epos - s) : 1);
    pooled[t] = acc / cnt;
    __syncthreads();

    if (t < 64) {
        float a = bh1[t];
        #pragma unroll 4
        for (int c = 0; c < HID; c++) a = fmaf(pooled[c], Wh1[c * 64 + t], a);
        hdn[t] = fmaxf(a, 0.f);
    }
    __syncthreads();

    if (t < 32) {
        float a = hdn[t] * Wh2[t] + hdn[t + 32] * Wh2[t + 32];
        #pragma unroll
        for (int off = 16; off; off >>= 1) a += __shfl_down_sync(0xffffffffu, a, off);
        if (t == 0) out[g] = a + bh2[0];
    }
}

// ---------------- launch ----------------
extern "C" void kernel_launch(void* const* d_in, const int* in_sizes, int n_in,
                              void* d_out, int out_size)
{
    const float* x       = (const float*)d_in[0];
    const int*   ei      = (const int*)d_in[1];
    const int*   batch   = (const int*)d_in[2];
    const float* W       = (const float*)d_in[3];
    const float* att_src = (const float*)d_in[4];
    const float* att_dst = (const float*)d_in[5];
    const float* bias    = (const float*)d_in[6];
    const float* gamma   = (const float*)d_in[7];
    const float* beta    = (const float*)d_in[8];
    const float* bn_mean = (const float*)d_in[9];
    const float* bn_var  = (const float*)d_in[10];
    const float* Wh1     = (const float*)d_in[11];
    const float* bh1     = (const float*)d_in[12];
    const float* Wh2     = (const float*)d_in[13];
    const float* bh2     = (const float*)d_in[14];

    int N = in_sizes[0] / HID;
    int E = in_sizes[1] / 2;
    int Etot = E + N;
    int G = out_size;

    const int GSMEM = 8192 * (int)sizeof(float4);   // 128KB
    cudaFuncSetAttribute(gemm_tf32_kernel, cudaFuncAttributeMaxDynamicSharedMemorySize, GSMEM);

    int gemm_blocks = (N + 127) / 128;
    int edge_blocks = (Etot + 255) / 256;
    int node_blocks = (N + 255) / 256;
    int scan_blocks = (N + 1023) / 1024;
    int agg_blocks  = (N * 32 + 255) / 256;   // warp per node

    // --- CSR build (once; reused by all 3 layers) ---
    zero_kernel<<<node_blocks, 256>>>(N);
    hist_kernel<<<edge_blocks, 256>>>(ei, E, Etot);
    scan1_kernel<<<scan_blocks, 1024>>>(N);
    scan2_kernel<<<1, 1024>>>(scan_blocks);
    scan3_kernel<<<node_blocks, 256>>>(N, Etot);
    scatter_kernel<<<edge_blocks, 256>>>(ei, E, Etot);

    for (int l = 0; l < 3; l++) {
        wfrag_kernel<<<16, 256>>>(W + (size_t)l * HID * HID);
        gemm_tf32_kernel<<<gemm_blocks, 256, GSMEM>>>(x, l > 0,
                                                      att_src + l * HID,
                                                      att_dst + l * HID, N);
        agg_kernel<<<agg_blocks, 256>>>(bias + l * HID,
                                        gamma + l * HID, beta + l * HID,
                                        bn_mean + l * HID, bn_var + l * HID, N);
    }
    pool_mlp_kernel<<<G, 128>>>(batch, Wh1, bh1, Wh2, bh2, (float*)d_out, N);
}

// round 6
// speedup vs baseline: 2.4887x; 1.1214x over previous
#include <cuda_runtime.h>
#include <cuda_bf16.h>
#include <math_constants.h>

// ---------------- problem constants ----------------
#define HID 128
#define HEADS 4
#define NEG_SLOPE 0.2f
#define BN_EPS 1e-5f
#define NMAX 100096
#define ETOTMAX 1800192

// ---------------- scratch (device globals; no allocation allowed) ----------
__device__ __align__(16) float g_h[NMAX * HID];      // h = x @ W
__device__ __align__(16) float g_xbuf[NMAX * HID];   // layer output / next input
__device__ __align__(16) float g_as[NMAX * HEADS];   // att_src dot
__device__ __align__(16) float g_ad[NMAX * HEADS];   // att_dst dot
__device__ __align__(16) float4 g_wfragh[3 * 4096];  // W hi (tf32) in mma B-frag order, per layer
__device__ __align__(16) float4 g_wfragl[3 * 4096];  // W lo residual (tf32)
// CSR scratch
__device__ int g_counts[NMAX];
__device__ int g_rowptr[NMAX + 1];
__device__ int g_fill[NMAX];
__device__ int g_csrc[ETOTMAX];
__device__ int g_bsum[1024];

__device__ __forceinline__ float lrelu(float v) { return v > 0.f ? v : NEG_SLOPE * v; }

__device__ __forceinline__ unsigned f2tf32(float f) {
    unsigned r;
    asm("cvt.rna.tf32.f32 %0, %1;" : "=r"(r) : "f"(f));
    return r;
}

__device__ __forceinline__ void mma_tf32(float* c, unsigned a0, unsigned a1,
                                         unsigned a2, unsigned a3,
                                         unsigned b0, unsigned b1) {
    asm volatile(
        "mma.sync.aligned.m16n8k8.row.col.f32.tf32.tf32.f32 "
        "{%0,%1,%2,%3},{%4,%5,%6,%7},{%8,%9},{%0,%1,%2,%3};"
        : "+f"(c[0]), "+f"(c[1]), "+f"(c[2]), "+f"(c[3])
        : "r"(a0), "r"(a1), "r"(a2), "r"(a3), "r"(b0), "r"(b1));
}

// ---------------- CSR build ----------------
__global__ void zero_kernel(int N)
{
    int i = blockIdx.x * blockDim.x + threadIdx.x;
    if (i < N) g_counts[i] = 0;
}

__global__ void hist_kernel(const int* __restrict__ ei, int E, int Etot)
{
    int i = blockIdx.x * blockDim.x + threadIdx.x;
    if (i >= Etot) return;
    int d = (i < E) ? ei[E + i] : (i - E);
    atomicAdd(&g_counts[d], 1);
}

__global__ void scan1_kernel(int N)
{
    __shared__ int sh[1024];
    int tid = threadIdx.x;
    int gid = blockIdx.x * 1024 + tid;
    int v = (gid < N) ? g_counts[gid] : 0;
    sh[tid] = v;
    __syncthreads();
    #pragma unroll
    for (int off = 1; off < 1024; off <<= 1) {
        int t = (tid >= off) ? sh[tid - off] : 0;
        __syncthreads();
        sh[tid] += t;
        __syncthreads();
    }
    if (gid <= N) g_rowptr[gid] = sh[tid] - v;   // exclusive
    if (tid == 1023) g_bsum[blockIdx.x] = sh[tid];
}

__global__ void scan2_kernel(int nb)
{
    __shared__ int sh[1024];
    int tid = threadIdx.x;
    int v = (tid < nb) ? g_bsum[tid] : 0;
    sh[tid] = v;
    __syncthreads();
    #pragma unroll
    for (int off = 1; off < 1024; off <<= 1) {
        int t = (tid >= off) ? sh[tid - off] : 0;
        __syncthreads();
        sh[tid] += t;
        __syncthreads();
    }
    if (tid < nb) g_bsum[tid] = sh[tid] - v;     // exclusive
}

__global__ void scan3_kernel(int N, int Etot)
{
    int gid = blockIdx.x * blockDim.x + threadIdx.x;
    if (gid < N) {
        int r = g_rowptr[gid] + g_bsum[gid >> 10];
        g_rowptr[gid] = r;
        g_fill[gid] = r;
    }
    if (gid == 0) g_rowptr[N] = Etot;
}

__global__ void scatter_kernel(const int* __restrict__ ei, int E, int Etot)
{
    int i = blockIdx.x * blockDim.x + threadIdx.x;
    if (i >= Etot) return;
    int s, d;
    if (i < E) { s = ei[i]; d = ei[E + i]; } else { s = d = i - E; }
    int pos = atomicAdd(&g_fill[d], 1);
    g_csrc[pos] = s;
}

// ---------------- W -> mma B-fragment order, hi/lo tf32 split, all layers ----
// layout per layer: frag[(ks*8 + v)*32 + lane] packs B frags for ntiles {2v,2v+1}
__global__ void wfrag_kernel(const float* __restrict__ Wbase)
{
    int gi = blockIdx.x * 256 + threadIdx.x;
    if (gi >= 3 * 4096) return;
    int l = gi >> 12;
    int i = gi & 4095;
    const float* W = Wbase + (size_t)l * HID * HID;
    int ks = i >> 8;
    int v = (i >> 5) & 7;
    int lane = i & 31;
    int krow = ks * 8 + (lane & 3);
    int n0 = (2 * v) * 8 + (lane >> 2);
    int n1 = n0 + 8;
    float w0 = W[krow * HID + n0];
    float w1 = W[(krow + 4) * HID + n0];
    float w2 = W[krow * HID + n1];
    float w3 = W[(krow + 4) * HID + n1];
    float4 hi, lo;
    hi.x = __uint_as_float(f2tf32(w0)); lo.x = __uint_as_float(f2tf32(w0 - hi.x));
    hi.y = __uint_as_float(f2tf32(w1)); lo.y = __uint_as_float(f2tf32(w1 - hi.y));
    hi.z = __uint_as_float(f2tf32(w2)); lo.z = __uint_as_float(f2tf32(w2 - hi.z));
    hi.w = __uint_as_float(f2tf32(w3)); lo.w = __uint_as_float(f2tf32(w3 - hi.w));
    g_wfragh[gi] = hi;
    g_wfragl[gi] = lo;
}

// ---------------- 3xTF32 tensor-core GEMM: h = x @ W[l] + attention dots ----
// block: 512 threads / 16 warps; block tile 256 rows x 128 cols.
// warp w owns rows [blk*256 + 16w, +16), all 128 cols (16 n-tiles of 8).
__global__ __launch_bounds__(512) void gemm_tf32_kernel(
    const float* __restrict__ xext, int use_xbuf, int layer,
    const float* __restrict__ att_s, const float* __restrict__ att_d, int N)
{
    extern __shared__ float4 sW[];      // [0,4096) hi, [4096,8192) lo : 128KB
    float4* sWh = sW;
    float4* sWl = sW + 4096;

    const float* __restrict__ x = use_xbuf ? g_xbuf : xext;
    const float4* wfh = g_wfragh + layer * 4096;
    const float4* wfl = g_wfragl + layer * 4096;

    int tid = threadIdx.x;
    int lane = tid & 31;
    int wid = tid >> 5;

    #pragma unroll 4
    for (int i = tid; i < 4096; i += 512) { sWh[i] = wfh[i]; sWl[i] = wfl[i]; }
    __syncthreads();

    int row0 = blockIdx.x * 256 + wid * 16;
    int g = lane >> 2;
    int cl = lane & 3;
    int r0 = row0 + g;
    int r1 = r0 + 8;
    bool v0 = r0 < N, v1 = r1 < N;

    float c[16][4];
    #pragma unroll
    for (int t = 0; t < 16; t++) {
        c[t][0] = 0.f; c[t][1] = 0.f; c[t][2] = 0.f; c[t][3] = 0.f;
    }

    const float* xr0 = x + (size_t)r0 * HID;
    const float* xr1 = x + (size_t)r1 * HID;

    for (int ks = 0; ks < 16; ks++) {
        int k0 = ks * 8 + cl;
        float f0 = v0 ? __ldg(xr0 + k0)     : 0.f;
        float f2 = v0 ? __ldg(xr0 + k0 + 4) : 0.f;
        float f1 = v1 ? __ldg(xr1 + k0)     : 0.f;
        float f3 = v1 ? __ldg(xr1 + k0 + 4) : 0.f;
        unsigned ah0 = f2tf32(f0), ah1 = f2tf32(f1), ah2 = f2tf32(f2), ah3 = f2tf32(f3);
        unsigned al0 = f2tf32(f0 - __uint_as_float(ah0));
        unsigned al1 = f2tf32(f1 - __uint_as_float(ah1));
        unsigned al2 = f2tf32(f2 - __uint_as_float(ah2));
        unsigned al3 = f2tf32(f3 - __uint_as_float(ah3));
        #pragma unroll
        for (int v = 0; v < 8; v++) {
            float4 bh = sWh[(ks * 8 + v) * 32 + lane];
            float4 bl = sWl[(ks * 8 + v) * 32 + lane];
            unsigned bh0 = __float_as_uint(bh.x), bh1 = __float_as_uint(bh.y);
            unsigned bh2 = __float_as_uint(bh.z), bh3 = __float_as_uint(bh.w);
            unsigned bl0 = __float_as_uint(bl.x), bl1 = __float_as_uint(bl.y);
            unsigned bl2 = __float_as_uint(bl.z), bl3 = __float_as_uint(bl.w);
            // Ah*Bh + Ah*Bl + Al*Bh
            mma_tf32(c[2 * v],     ah0, ah1, ah2, ah3, bh0, bh1);
            mma_tf32(c[2 * v],     ah0, ah1, ah2, ah3, bl0, bl1);
            mma_tf32(c[2 * v],     al0, al1, al2, al3, bh0, bh1);
            mma_tf32(c[2 * v + 1], ah0, ah1, ah2, ah3, bh2, bh3);
            mma_tf32(c[2 * v + 1], ah0, ah1, ah2, ah3, bl2, bl3);
            mma_tf32(c[2 * v + 1], al0, al1, al2, al3, bh2, bh3);
        }
    }

    // store h (fp32)
    #pragma unroll
    for (int nt = 0; nt < 16; nt++) {
        int cb = nt * 8 + cl * 2;
        if (v0) *(float2*)&g_h[(size_t)r0 * HID + cb] = make_float2(c[nt][0], c[nt][1]);
        if (v1) *(float2*)&g_h[(size_t)r1 * HID + cb] = make_float2(c[nt][2], c[nt][3]);
    }

    // attention dots per head (head h = ntiles 4h..4h+3)
    #pragma unroll
    for (int h = 0; h < HEADS; h++) {
        float s0 = 0.f, d0 = 0.f, s1 = 0.f, d1 = 0.f;
        #pragma unroll
        for (int t = 0; t < 4; t++) {
            int nt = h * 4 + t;
            int cb = nt * 8 + cl * 2;
            float w0 = att_s[cb], w1 = att_s[cb + 1];
            float u0 = att_d[cb], u1 = att_d[cb + 1];
            s0 += c[nt][0] * w0 + c[nt][1] * w1;
            d0 += c[nt][0] * u0 + c[nt][1] * u1;
            s1 += c[nt][2] * w0 + c[nt][3] * w1;
            d1 += c[nt][2] * u0 + c[nt][3] * u1;
        }
        s0 += __shfl_down_sync(0xffffffffu, s0, 2, 4); s0 += __shfl_down_sync(0xffffffffu, s0, 1, 4);
        d0 += __shfl_down_sync(0xffffffffu, d0, 2, 4); d0 += __shfl_down_sync(0xffffffffu, d0, 1, 4);
        s1 += __shfl_down_sync(0xffffffffu, s1, 2, 4); s1 += __shfl_down_sync(0xffffffffu, s1, 1, 4);
        d1 += __shfl_down_sync(0xffffffffu, d1, 2, 4); d1 += __shfl_down_sync(0xffffffffu, d1, 1, 4);
        if (cl == 0) {
            if (v0) { g_as[r0 * HEADS + h] = s0; g_ad[r0 * HEADS + h] = d0; }
            if (v1) { g_as[r1 * HEADS + h] = s1; g_ad[r1 * HEADS + h] = d1; }
        }
    }
}

// ---------------- fused aggregation: 2-chain online softmax + weighted sum + bias + relu + BN
__global__ __launch_bounds__(256) void agg_kernel(const float* __restrict__ bias,
                           const float* __restrict__ gamma, const float* __restrict__ beta,
                           const float* __restrict__ mean, const float* __restrict__ var,
                           int N)
{
    int w = (blockIdx.x * blockDim.x + threadIdx.x) >> 5;
    int lane = threadIdx.x & 31;
    if (w >= N) return;
    int n = w;
    int h = lane >> 3;

    int beg = g_rowptr[n];
    int end = g_rowptr[n + 1];
    float ad_h = g_ad[n * HEADS + h];

    // two independent online-softmax chains
    float m0 = -CUDART_INF_F, m1 = -CUDART_INF_F;
    float d0 = 0.f, d1 = 0.f;
    float4 A0 = make_float4(0.f, 0.f, 0.f, 0.f);
    float4 A1 = make_float4(0.f, 0.f, 0.f, 0.f);

    int i = beg;
    for (; i + 1 < end; i += 2) {
        int sa = g_csrc[i];
        int sb = g_csrc[i + 1];
        float asa = __ldg(&g_as[sa * HEADS + h]);
        float asb = __ldg(&g_as[sb * HEADS + h]);
        float4 ha = ((const float4*)g_h)[(size_t)sa * 32 + lane];
        float4 hb = ((const float4*)g_h)[(size_t)sb * 32 + lane];

        float ea = lrelu(asa + ad_h);
        float nm0 = fmaxf(m0, ea);
        float sc0 = __expf(m0 - nm0);
        float pa  = __expf(ea - nm0);
        d0 = d0 * sc0 + pa;
        A0.x = A0.x * sc0 + pa * ha.x;
        A0.y = A0.y * sc0 + pa * ha.y;
        A0.z = A0.z * sc0 + pa * ha.z;
        A0.w = A0.w * sc0 + pa * ha.w;
        m0 = nm0;

        float eb = lrelu(asb + ad_h);
        float nm1 = fmaxf(m1, eb);
        float sc1 = __expf(m1 - nm1);
        float pb  = __expf(eb - nm1);
        d1 = d1 * sc1 + pb;
        A1.x = A1.x * sc1 + pb * hb.x;
        A1.y = A1.y * sc1 + pb * hb.y;
        A1.z = A1.z * sc1 + pb * hb.z;
        A1.w = A1.w * sc1 + pb * hb.w;
        m1 = nm1;
    }
    if (i < end) {
        int sa = g_csrc[i];
        float asa = __ldg(&g_as[sa * HEADS + h]);
        float4 ha = ((const float4*)g_h)[(size_t)sa * 32 + lane];
        float ea = lrelu(asa + ad_h);
        float nm0 = fmaxf(m0, ea);
        float sc0 = __expf(m0 - nm0);
        float pa  = __expf(ea - nm0);
        d0 = d0 * sc0 + pa;
        A0.x = A0.x * sc0 + pa * ha.x;
        A0.y = A0.y * sc0 + pa * ha.y;
        A0.z = A0.z * sc0 + pa * ha.z;
        A0.w = A0.w * sc0 + pa * ha.w;
        m0 = nm0;
    }

    // merge chains (deg >= 1 guaranteed by self-loops, so m0 or m1 finite)
    float m = fmaxf(m0, m1);
    float s0 = __expf(m0 - m);
    float s1 = __expf(m1 - m);
    float den = d0 * s0 + d1 * s1;
    float4 acc;
    acc.x = A0.x * s0 + A1.x * s1;
    acc.y = A0.y * s0 + A1.y * s1;
    acc.z = A0.z * s0 + A1.z * s1;
    acc.w = A0.w * s0 + A1.w * s1;

    float inv = 1.f / (den + 1e-16f);
    float4 b4 = ((const float4*)bias)[lane];
    float4 gm = ((const float4*)gamma)[lane];
    float4 bt = ((const float4*)beta)[lane];
    float4 mu = ((const float4*)mean)[lane];
    float4 vr = ((const float4*)var)[lane];

    float4 r;
    r.x = (fmaxf(acc.x * inv + b4.x, 0.f) - mu.x) * (gm.x * rsqrtf(vr.x + BN_EPS)) + bt.x;
    r.y = (fmaxf(acc.y * inv + b4.y, 0.f) - mu.y) * (gm.y * rsqrtf(vr.y + BN_EPS)) + bt.y;
    r.z = (fmaxf(acc.z * inv + b4.z, 0.f) - mu.z) * (gm.z * rsqrtf(vr.z + BN_EPS)) + bt.z;
    r.w = (fmaxf(acc.w * inv + b4.w, 0.f) - mu.w) * (gm.w * rsqrtf(vr.w + BN_EPS)) + bt.w;
    ((float4*)g_xbuf)[(size_t)n * 32 + lane] = r;
}

// ---------------- pool (batch is sorted) + MLP head ----------------
__global__ void pool_mlp_kernel(const int* __restrict__ batch,
                                const float* __restrict__ Wh1, const float* __restrict__ bh1,
                                const float* __restrict__ Wh2, const float* __restrict__ bh2,
                                float* __restrict__ out, int N)
{
    int g = blockIdx.x;
    int t = threadIdx.x;   // 128 threads
    __shared__ float pooled[HID];
    __shared__ float hdn[64];
    __shared__ int bounds[2];

    if (t < 2) {
        int target = g + t;
        int lo = 0, hi = N;
        while (lo < hi) {
            int mid = (lo + hi) >> 1;
            if (batch[mid] < target) lo = mid + 1; else hi = mid;
        }
        bounds[t] = lo;
    }
    __syncthreads();
    int s = bounds[0], epos = bounds[1];

    float acc = 0.f;
    for (int n = s; n < epos; n++) acc += g_xbuf[(size_t)n * HID + t];
    float cnt = (float)((epos - s) > 1 ? (epos - s) : 1);
    pooled[t] = acc / cnt;
    __syncthreads();

    if (t < 64) {
        float a = bh1[t];
        #pragma unroll 4
        for (int c = 0; c < HID; c++) a = fmaf(pooled[c], Wh1[c * 64 + t], a);
        hdn[t] = fmaxf(a, 0.f);
    }
    __syncthreads();

    if (t < 32) {
        float a = hdn[t] * Wh2[t] + hdn[t + 32] * Wh2[t + 32];
        #pragma unroll
        for (int off = 16; off; off >>= 1) a += __shfl_down_sync(0xffffffffu, a, off);
        if (t == 0) out[g] = a + bh2[0];
    }
}

// ---------------- launch ----------------
extern "C" void kernel_launch(void* const* d_in, const int* in_sizes, int n_in,
                              void* d_out, int out_size)
{
    const float* x       = (const float*)d_in[0];
    const int*   ei      = (const int*)d_in[1];
    const int*   batch   = (const int*)d_in[2];
    const float* W       = (const float*)d_in[3];
    const float* att_src = (const float*)d_in[4];
    const float* att_dst = (const float*)d_in[5];
    const float* bias    = (const float*)d_in[6];
    const float* gamma   = (const float*)d_in[7];
    const float* beta    = (const float*)d_in[8];
    const float* bn_mean = (const float*)d_in[9];
    const float* bn_var  = (const float*)d_in[10];
    const float* Wh1     = (const float*)d_in[11];
    const float* bh1     = (const float*)d_in[12];
    const float* Wh2     = (const float*)d_in[13];
    const float* bh2     = (const float*)d_in[14];

    int N = in_sizes[0] / HID;
    int E = in_sizes[1] / 2;
    int Etot = E + N;
    int G = out_size;

    const int GSMEM = 8192 * (int)sizeof(float4);   // 128KB
    cudaFuncSetAttribute(gemm_tf32_kernel, cudaFuncAttributeMaxDynamicSharedMemorySize, GSMEM);

    int gemm_blocks = (N + 255) / 256;
    int edge_blocks = (Etot + 255) / 256;
    int node_blocks = (N + 255) / 256;
    int scan_blocks = (N + 1023) / 1024;
    int agg_blocks  = (N * 32 + 255) / 256;   // warp per node

    // --- W fragments for all layers + CSR build (once) ---
    wfrag_kernel<<<48, 256>>>(W);
    zero_kernel<<<node_blocks, 256>>>(N);
    hist_kernel<<<edge_blocks, 256>>>(ei, E, Etot);
    scan1_kernel<<<scan_blocks, 1024>>>(N);
    scan2_kernel<<<1, 1024>>>(scan_blocks);
    scan3_kernel<<<node_blocks, 256>>>(N, Etot);
    scatter_kernel<<<edge_blocks, 256>>>(ei, E, Etot);

    for (int l = 0; l < 3; l++) {
        gemm_tf32_kernel<<<gemm_blocks, 512, GSMEM>>>(x, l > 0, l,
                                                      att_src + l * HID,
                                                      att_dst + l * HID, N);
        agg_kernel<<<agg_blocks, 256>>>(bias + l * HID,
                                        gamma + l * HID, beta + l * HID,
                                        bn_mean + l * HID, bn_var + l * HID, N);
    }
    pool_mlp_kernel<<<G, 128>>>(batch, Wh1, bh1, Wh2, bh2, (float*)d_out, N);
}